// round 2
// baseline (speedup 1.0000x reference)
#include <cuda_runtime.h>
#include <math.h>

#define BN 512
#define SN 200
#define HN 512
#define AN 32
#define MN (BN*SN)          // 102400
#define NEGV (-1e9f)

// ---------------- scratch (no allocations allowed) ----------------
__device__ float g_moe[(size_t)MN*HN];   // 210 MB
__device__ float g_bij[MN*AN];
__device__ float g_w[MN];
__device__ float g_tma[MN];
__device__ int   g_cnt[BN*AN];

__device__ __forceinline__ float wsum(float v){
#pragma unroll
    for (int o=16;o;o>>=1) v += __shfl_xor_sync(0xffffffffu, v, o);
    return v;
}
__device__ __forceinline__ float wmax(float v){
#pragma unroll
    for (int o=16;o;o>>=1) v = fmaxf(v, __shfl_xor_sync(0xffffffffu, v, o));
    return v;
}

// ---------------- K0: zero counts ----------------
__global__ void k_zero(){
    int i = blockIdx.x*256 + threadIdx.x;
    if (i < BN*AN) g_cnt[i] = 0;
}

// ---------------- K1: attention GEMM fused with leakyrelu + dot(w2) ----------------
// w[m] = sum_n leakyrelu( (x_m + pos) . W1[:,n] + b1[n] ) * w2[n]
__global__ __launch_bounds__(256) void k_attn(
    const float* __restrict__ X, const float* __restrict__ P,
    const float* __restrict__ W1, const float* __restrict__ b1,
    const float* __restrict__ w2)
{
    __shared__ __align__(16) float As[16][68];
    __shared__ __align__(16) float Bs[16][128];
    const int tid  = threadIdx.x;
    const int lane = tid & 31, wy = tid >> 5;
    const int m0   = blockIdx.x * 64;
    const int ar   = tid >> 2;              // 0..63 row within tile
    const int ak   = (tid & 3) * 4;         // k sub-offset
    const int gm   = m0 + ar;
    const int sA   = gm % SN;
    const int bk   = tid >> 4;              // 0..15
    const int bn   = (tid & 15) * 8;        // 0..120

    float wp[8];
#pragma unroll
    for (int r=0;r<8;r++) wp[r] = 0.f;

    for (int nc=0; nc<4; nc++){
        float acc[8][4];
#pragma unroll
        for (int r=0;r<8;r++)
#pragma unroll
            for (int c=0;c<4;c++) acc[r][c] = 0.f;

        for (int kt=0; kt<32; kt++){
            const int k0 = kt*16;
            float4 av = *reinterpret_cast<const float4*>(X + (size_t)gm*HN + k0 + ak);
            float4 pv = *reinterpret_cast<const float4*>(P + (size_t)sA*HN + k0 + ak);
            av.x += pv.x; av.y += pv.y; av.z += pv.z; av.w += pv.w;
            float4 bv0 = *reinterpret_cast<const float4*>(W1 + (size_t)(k0+bk)*HN + nc*128 + bn);
            float4 bv1 = *reinterpret_cast<const float4*>(W1 + (size_t)(k0+bk)*HN + nc*128 + bn + 4);
            __syncthreads();
            As[ak+0][ar]=av.x; As[ak+1][ar]=av.y; As[ak+2][ar]=av.z; As[ak+3][ar]=av.w;
            *reinterpret_cast<float4*>(&Bs[bk][bn])   = bv0;
            *reinterpret_cast<float4*>(&Bs[bk][bn+4]) = bv1;
            __syncthreads();
#pragma unroll
            for (int kk=0;kk<16;kk++){
                float4 a0 = *reinterpret_cast<const float4*>(&As[kk][wy*8]);
                float4 a1 = *reinterpret_cast<const float4*>(&As[kk][wy*8+4]);
                float4 bb = *reinterpret_cast<const float4*>(&Bs[kk][lane*4]);
                float ra[8] = {a0.x,a0.y,a0.z,a0.w,a1.x,a1.y,a1.z,a1.w};
                float rb[4] = {bb.x,bb.y,bb.z,bb.w};
#pragma unroll
                for (int r=0;r<8;r++)
#pragma unroll
                    for (int c=0;c<4;c++) acc[r][c] += ra[r]*rb[c];
            }
        }
        // epilogue: leakyrelu + dot with w2
#pragma unroll
        for (int c=0;c<4;c++){
            const int n = nc*128 + lane*4 + c;
            const float bb1 = __ldg(b1+n);
            const float ww2 = __ldg(w2+n);
#pragma unroll
            for (int r=0;r<8;r++){
                float v = acc[r][c] + bb1;
                v = v > 0.f ? v : 0.01f*v;
                wp[r] += v * ww2;
            }
        }
    }
#pragma unroll
    for (int r=0;r<8;r++){
        float t = wsum(wp[r]);
        if (lane==0) g_w[m0 + wy*8 + r] = t;
    }
}

// ---------------- K2: masked softmax over S -> tma ----------------
__global__ __launch_bounds__(256) void k_softw(const int* __restrict__ seq,
                                               const float* __restrict__ b2)
{
    const int b = blockIdx.x, tid = threadIdx.x;
    const int lane = tid & 31, wid = tid >> 5;
    __shared__ float shm[8], shs[8];
    const bool act = tid < SN;
    float myw = NEGV;
    if (act){
        const int m = b*SN + tid;
        myw = (seq[m]==0) ? NEGV : (g_w[m] + b2[0]);
    }
    float v = wmax(myw);
    if (lane==0) shm[wid] = v;
    __syncthreads();
    float mx = shm[0];
#pragma unroll
    for (int i=1;i<8;i++) mx = fmaxf(mx, shm[i]);
    float e = act ? expf(myw - mx) : 0.f;
    float s = wsum(e);
    if (lane==0) shs[wid] = s;
    __syncthreads();
    float tot = shs[0];
#pragma unroll
    for (int i=1;i<8;i++) tot += shs[i];
    if (act) g_tma[b*SN + tid] = e / tot;
}

// ---------------- K3: gates GEMM + softmax out + argmax count + bij init ----------------
__global__ __launch_bounds__(128) void k_gates(
    const float* __restrict__ X, const int* __restrict__ seq,
    const float* __restrict__ AW, float* __restrict__ og)
{
    __shared__ __align__(16) float Ws[16*512];
    const int row = blockIdx.x*128 + threadIdx.x;
    float acc[32];
#pragma unroll
    for (int a=0;a<32;a++) acc[a] = 0.f;

#pragma unroll
    for (int ch=0; ch<2; ch++){
        __syncthreads();
        for (int i=threadIdx.x; i<2048; i+=128)
            reinterpret_cast<float4*>(Ws)[i] = reinterpret_cast<const float4*>(AW)[ch*2048 + i];
        __syncthreads();
        const float4* xr = reinterpret_cast<const float4*>(X + (size_t)row*HN);
        for (int k4=0;k4<128;k4++){
            float4 x = xr[k4];
#pragma unroll
            for (int a=0;a<16;a++){
                float4 w = reinterpret_cast<const float4*>(Ws)[a*128 + k4];
                acc[ch*16+a] += x.x*w.x + x.y*w.y + x.z*w.z + x.w*w.w;
            }
        }
    }
    // argmax (first max, like jnp.argmax)
    float mx = acc[0]; int am = 0;
#pragma unroll
    for (int a=1;a<32;a++) if (acc[a] > mx){ mx = acc[a]; am = a; }
    // softmax over aspects -> output
    float e[32]; float s = 0.f;
#pragma unroll
    for (int a=0;a<32;a++){ e[a] = expf(acc[a]-mx); s += e[a]; }
    const float inv = 1.f/s;
#pragma unroll
    for (int a=0;a<32;a++){
        og[(size_t)row*AN + a]    = e[a]*inv;
        g_bij[(size_t)row*AN + a] = acc[a];
    }
    const int b = row / SN;
    if (seq[row] != 0) atomicAdd(&g_cnt[b*AN + am], 1);
}

// ---------------- K4: moe GEMM (tanh + residual, pre-LN) ----------------
__global__ __launch_bounds__(256) void k_moe(
    const float* __restrict__ X, const float* __restrict__ W,
    const float* __restrict__ bL)
{
    __shared__ __align__(16) float As[16][68];
    __shared__ __align__(16) float Bs[16][128];
    const int tid  = threadIdx.x;
    const int lane = tid & 31, wy = tid >> 5;
    const int m0   = blockIdx.x * 64;
    const int nc   = blockIdx.y;
    const int ar   = tid >> 2;
    const int ak   = (tid & 3) * 4;
    const int gm   = m0 + ar;
    const int bk   = tid >> 4;
    const int bn   = (tid & 15) * 8;

    float acc[8][4];
#pragma unroll
    for (int r=0;r<8;r++)
#pragma unroll
        for (int c=0;c<4;c++) acc[r][c] = 0.f;

    for (int kt=0; kt<32; kt++){
        const int k0 = kt*16;
        float4 av  = *reinterpret_cast<const float4*>(X + (size_t)gm*HN + k0 + ak);
        float4 bv0 = *reinterpret_cast<const float4*>(W + (size_t)(k0+bk)*HN + nc*128 + bn);
        float4 bv1 = *reinterpret_cast<const float4*>(W + (size_t)(k0+bk)*HN + nc*128 + bn + 4);
        __syncthreads();
        As[ak+0][ar]=av.x; As[ak+1][ar]=av.y; As[ak+2][ar]=av.z; As[ak+3][ar]=av.w;
        *reinterpret_cast<float4*>(&Bs[bk][bn])   = bv0;
        *reinterpret_cast<float4*>(&Bs[bk][bn+4]) = bv1;
        __syncthreads();
#pragma unroll
        for (int kk=0;kk<16;kk++){
            float4 a0 = *reinterpret_cast<const float4*>(&As[kk][wy*8]);
            float4 a1 = *reinterpret_cast<const float4*>(&As[kk][wy*8+4]);
            float4 bb = *reinterpret_cast<const float4*>(&Bs[kk][lane*4]);
            float ra[8] = {a0.x,a0.y,a0.z,a0.w,a1.x,a1.y,a1.z,a1.w};
            float rb[4] = {bb.x,bb.y,bb.z,bb.w};
#pragma unroll
            for (int r=0;r<8;r++)
#pragma unroll
                for (int c=0;c<4;c++) acc[r][c] += ra[r]*rb[c];
        }
    }
#pragma unroll
    for (int c=0;c<4;c++){
        const int n = nc*128 + lane*4 + c;
        const float bb = __ldg(bL+n);
#pragma unroll
        for (int r=0;r<8;r++){
            const int rr = m0 + wy*8 + r;
            float v = tanhf(acc[r][c] + bb) + __ldg(X + (size_t)rr*HN + n);
            g_moe[(size_t)rr*HN + n] = v;
        }
    }
}

// ---------------- K5: LayerNorm in place on g_moe ----------------
__global__ __launch_bounds__(128) void k_ln(const float* __restrict__ gam,
                                            const float* __restrict__ bet)
{
    const int row = blockIdx.x, tid = threadIdx.x;
    const int lane = tid & 31, wid = tid >> 5;
    __shared__ float sh1[4], sh2[4];
    float4 x = reinterpret_cast<const float4*>(g_moe)[(size_t)row*128 + tid];
    float s = x.x + x.y + x.z + x.w;
    s = wsum(s);
    if (lane==0) sh1[wid] = s;
    __syncthreads();
    const float mu = (sh1[0]+sh1[1]+sh1[2]+sh1[3]) * (1.f/512.f);
    const float d0=x.x-mu, d1=x.y-mu, d2=x.z-mu, d3=x.w-mu;
    float q = d0*d0 + d1*d1 + d2*d2 + d3*d3;
    q = wsum(q);
    if (lane==0) sh2[wid] = q;
    __syncthreads();
    const float var = (sh2[0]+sh2[1]+sh2[2]+sh2[3]) * (1.f/512.f);
    const float r = rsqrtf(var + 1e-12f);
    float4 gg = __ldg(reinterpret_cast<const float4*>(gam) + tid);
    float4 bb = __ldg(reinterpret_cast<const float4*>(bet) + tid);
    float4 o;
    o.x = d0*r*gg.x + bb.x;
    o.y = d1*r*gg.y + bb.y;
    o.z = d2*r*gg.z + bb.z;
    o.w = d3*r*gg.w + bb.w;
    reinterpret_cast<float4*>(g_moe)[(size_t)row*128 + tid] = o;
}

// ---------------- mask output ----------------
__global__ void k_mask(float* __restrict__ om){
    int i = blockIdx.x*256 + threadIdx.x;
    if (i < BN*AN) om[i] = (g_cnt[i]==0) ? 1.f : 0.f;
}

// ---------------- routing: cap = einsum(softmax-masked(bij)*tma, moe) + squash ----------------
// cij computed inline: warp ty handles source row s = st+ty, lane = aspect.
__global__ __launch_bounds__(256) void k_cap(const int* __restrict__ seq,
                                             float* __restrict__ oc){
    __shared__ __align__(16) float Ms[8][512];
    __shared__ __align__(16) float Ct[8][32];
    const int b = blockIdx.x, tid = threadIdx.x;
    const int lane = tid & 31, ty = tid >> 5;   // ty: source-row / 4-aspect group
    float acc[4][16];
#pragma unroll
    for (int a=0;a<4;a++)
#pragma unroll
        for (int t=0;t<16;t++) acc[a][t] = 0.f;

    const float maskNeg[1] = {NEGV};
    (void)maskNeg;

    for (int st=0; st<SN; st+=8){
        __syncthreads();
#pragma unroll
        for (int k=0;k<4;k++){
            const int f  = tid + k*256;     // float4 index 0..1023
            const int rr = f >> 7;          // row 0..7
            const int cc = (f & 127) << 2;  // col
            *reinterpret_cast<float4*>(&Ms[rr][cc]) =
                *reinterpret_cast<const float4*>(&g_moe[(size_t)(b*SN + st + rr)*HN + cc]);
        }
        {
            // fused cij: masked softmax over 32 aspects within the warp
            const size_t m = (size_t)b*SN + st + ty;
            float x = g_bij[m*AN + lane];
            if (g_cnt[b*AN + lane] == 0) x = NEGV;
            const float mx = wmax(x);
            const float e  = expf(x - mx);
            const float sm = wsum(e);
            float cij = (seq[m]==0) ? 0.f : e/sm;
            Ct[ty][lane] = cij * g_tma[m];
        }
        __syncthreads();
#pragma unroll
        for (int sp=0; sp<8; sp++){
            float4 c4 = *reinterpret_cast<const float4*>(&Ct[sp][ty*4]);
            float cv[4] = {c4.x, c4.y, c4.z, c4.w};
#pragma unroll
            for (int j=0;j<4;j++){
                float4 mv = *reinterpret_cast<const float4*>(&Ms[sp][lane*4 + j*128]);
#pragma unroll
                for (int a=0;a<4;a++){
                    acc[a][j*4+0] += cv[a]*mv.x;
                    acc[a][j*4+1] += cv[a]*mv.y;
                    acc[a][j*4+2] += cv[a]*mv.z;
                    acc[a][j*4+3] += cv[a]*mv.w;
                }
            }
        }
    }
    // squash per aspect row
#pragma unroll
    for (int a=0;a<4;a++){
        float q = 0.f;
#pragma unroll
        for (int t=0;t<16;t++) q += acc[a][t]*acc[a][t];
        q = wsum(q);
        const float sc = q/(1.f+q) * rsqrtf(q + 1e-9f);
        const int ga = b*AN + ty*4 + a;
#pragma unroll
        for (int j=0;j<4;j++){
            float4 o = make_float4(acc[a][j*4+0]*sc, acc[a][j*4+1]*sc,
                                   acc[a][j*4+2]*sc, acc[a][j*4+3]*sc);
            *reinterpret_cast<float4*>(&oc[(size_t)ga*HN + lane*4 + j*128]) = o;
        }
    }
}

// ---------------- routing: bij += moe . cap^T ----------------
__global__ __launch_bounds__(256) void k_bup(const float* __restrict__ cap){
    const int b = blockIdx.x, s = threadIdx.x;
    if (s >= SN) return;
    const size_t m = (size_t)b*SN + s;
    const float4* xr = reinterpret_cast<const float4*>(g_moe + m*HN);
    const float4* cr = reinterpret_cast<const float4*>(cap + (size_t)b*AN*HN);
    float accb[32];
#pragma unroll
    for (int a=0;a<32;a++) accb[a] = 0.f;
    for (int k4=0;k4<128;k4++){
        float4 x = xr[k4];
#pragma unroll
        for (int a=0;a<32;a++){
            float4 c = __ldg(&cr[a*128 + k4]);
            accb[a] += x.x*c.x + x.y*c.y + x.z*c.z + x.w*c.w;
        }
    }
#pragma unroll
    for (int a=0;a<32;a++) g_bij[m*AN + a] += accb[a];
}

// ---------------- launch ----------------
extern "C" void kernel_launch(void* const* d_in, const int* in_sizes, int n_in,
                              void* d_out, int out_size)
{
    const float* item_emb = (const float*)d_in[0];
    const int*   item_seq = (const int*)  d_in[1];
    const float* pos_emb  = (const float*)d_in[2];
    const float* attn_w1  = (const float*)d_in[3];
    const float* attn_b1  = (const float*)d_in[4];
    const float* attn_w2  = (const float*)d_in[5];
    const float* attn_b2  = (const float*)d_in[6];
    const float* lin_w    = (const float*)d_in[7];
    const float* lin_b    = (const float*)d_in[8];
    const float* aspect_w = (const float*)d_in[9];
    const float* ln_g     = (const float*)d_in[10];
    const float* ln_b     = (const float*)d_in[11];

    float* out       = (float*)d_out;
    float* out_cap   = out;                                   // B*A*H
    float* out_gates = out + (size_t)BN*AN*HN;                // B*S*A
    float* out_mask  = out_gates + (size_t)BN*SN*AN;          // B*A

    k_zero<<<64,256>>>();
    k_attn<<<1600,256>>>(item_emb, pos_emb, attn_w1, attn_b1, attn_w2);
    k_softw<<<BN,256>>>(item_seq, attn_b2);
    k_gates<<<800,128>>>(item_emb, item_seq, aspect_w, out_gates);
    dim3 g4(1600,4);
    k_moe<<<g4,256>>>(item_emb, lin_w, lin_b);
    k_ln<<<MN,128>>>(ln_g, ln_b);
    k_mask<<<64,256>>>(out_mask);
    for (int it=0; it<3; it++){
        k_cap<<<BN,256>>>(item_seq, out_cap);
        if (it < 2) k_bup<<<BN,256>>>(out_cap);
    }
}

// round 3
// speedup vs baseline: 1.7128x; 1.7128x over previous
#include <cuda_runtime.h>
#include <math.h>
#include <stdint.h>

#define BN 512
#define SN 200
#define HN 512
#define AN 32
#define MN (BN*SN)          // 102400
#define NEGV (-1e9f)

// ---------------- scratch (no allocations allowed) ----------------
__device__ float g_moe[(size_t)MN*HN];   // 210 MB
__device__ float g_bij[MN*AN];
__device__ float g_w[MN];
__device__ float g_tma[MN];
__device__ int   g_cnt[BN*AN];

__device__ __forceinline__ float wsum(float v){
#pragma unroll
    for (int o=16;o;o>>=1) v += __shfl_xor_sync(0xffffffffu, v, o);
    return v;
}
__device__ __forceinline__ float wmax(float v){
#pragma unroll
    for (int o=16;o;o>>=1) v = fmaxf(v, __shfl_xor_sync(0xffffffffu, v, o));
    return v;
}

__device__ __forceinline__ uint32_t f2tf(float f){
    uint32_t r; asm("cvt.rna.tf32.f32 %0, %1;" : "=r"(r) : "f"(f)); return r;
}
__device__ __forceinline__ void tfsplit(float x, uint32_t& h, uint32_t& l){
    h = f2tf(x);
    l = f2tf(x - __uint_as_float(h));
}
__device__ __forceinline__ void mma8(float* c, const uint32_t* a, const uint32_t* b){
    asm volatile("mma.sync.aligned.m16n8k8.row.col.f32.tf32.tf32.f32 "
      "{%0,%1,%2,%3},{%4,%5,%6,%7},{%8,%9},{%0,%1,%2,%3};"
      : "+f"(c[0]),"+f"(c[1]),"+f"(c[2]),"+f"(c[3])
      : "r"(a[0]),"r"(a[1]),"r"(a[2]),"r"(a[3]),"r"(b[0]),"r"(b[1]));
}

// ---------------- K0: zero counts ----------------
__global__ void k_zero(){
    int i = blockIdx.x*256 + threadIdx.x;
    if (i < BN*AN) g_cnt[i] = 0;
}

// ============================================================================
// K1: attention GEMM (TF32 tensor core) fused with leakyrelu + dot(w2)
// w[m] = sum_n leakyrelu( (x_m + pos) . W1[:,n] + b1[n] ) * w2[n]
// Block: 128 rows; loops nc over 4 N-chunks of 128; K staged in 32s.
// ============================================================================
__global__ __launch_bounds__(256) void k_attn_tc(
    const float* __restrict__ X, const float* __restrict__ P,
    const float* __restrict__ W1, const float* __restrict__ b1,
    const float* __restrict__ w2)
{
    __shared__ uint32_t As[128][36];
    __shared__ uint32_t Bs[32][132];
    __shared__ float wps[128];
    const int tid=threadIdx.x, lane=tid&31, wid=tid>>5;
    const int wm=wid>>2, wn=wid&3, g=lane>>2, tig=lane&3;
    const int m0=blockIdx.x*128;
    const int lar=tid>>3, lac=(tid&7)*4;       // A loader: 4 rows (it*32), 16B cols
    const int lbk=tid>>5, lbc=(tid&31)*4;      // B loader

    if(tid<128) wps[tid]=0.f;

    int grow[4], srow[4];
#pragma unroll
    for(int it=0;it<4;it++){ grow[it]=m0+lar+it*32; srow[it]=grow[it]%SN; }

    float wp[4][2];
#pragma unroll
    for(int mt=0;mt<4;mt++){ wp[mt][0]=0.f; wp[mt][1]=0.f; }

    float4 ra[4], rb[4];

    for(int nc=0;nc<4;nc++){
        float acc[4][4][4];
#pragma unroll
        for(int mt=0;mt<4;mt++)
#pragma unroll
            for(int nt=0;nt<4;nt++)
#pragma unroll
                for(int c=0;c<4;c++) acc[mt][nt][c]=0.f;

        // prologue load stage 0
#pragma unroll
        for(int it=0;it<4;it++){
            float4 xv=*(const float4*)(X+(size_t)grow[it]*HN+lac);
            float4 pv=*(const float4*)(P+(size_t)srow[it]*HN+lac);
            ra[it]=make_float4(xv.x+pv.x, xv.y+pv.y, xv.z+pv.z, xv.w+pv.w);
        }
#pragma unroll
        for(int it=0;it<4;it++)
            rb[it]=*(const float4*)(W1+(size_t)(lbk+it*8)*HN+nc*128+lbc);

#pragma unroll 1
        for(int kt=0;kt<16;kt++){
            __syncthreads();
#pragma unroll
            for(int it=0;it<4;it++)
                *(uint4*)&As[lar+it*32][lac] =
                    make_uint4(f2tf(ra[it].x),f2tf(ra[it].y),f2tf(ra[it].z),f2tf(ra[it].w));
#pragma unroll
            for(int it=0;it<4;it++)
                *(uint4*)&Bs[lbk+it*8][lbc] =
                    make_uint4(f2tf(rb[it].x),f2tf(rb[it].y),f2tf(rb[it].z),f2tf(rb[it].w));
            __syncthreads();
            if(kt<15){
                const int k0=(kt+1)*32;
#pragma unroll
                for(int it=0;it<4;it++){
                    float4 xv=*(const float4*)(X+(size_t)grow[it]*HN+k0+lac);
                    float4 pv=*(const float4*)(P+(size_t)srow[it]*HN+k0+lac);
                    ra[it]=make_float4(xv.x+pv.x, xv.y+pv.y, xv.z+pv.z, xv.w+pv.w);
                }
#pragma unroll
                for(int it=0;it<4;it++)
                    rb[it]=*(const float4*)(W1+(size_t)(k0+lbk+it*8)*HN+nc*128+lbc);
            }
#pragma unroll
            for(int ks=0;ks<4;ks++){
                uint32_t af[4][4], bf[4][2];
#pragma unroll
                for(int mt=0;mt<4;mt++){
                    const int r0=wm*64+mt*16;
                    af[mt][0]=As[r0+g  ][ks*8+tig];
                    af[mt][1]=As[r0+g+8][ks*8+tig];
                    af[mt][2]=As[r0+g  ][ks*8+tig+4];
                    af[mt][3]=As[r0+g+8][ks*8+tig+4];
                }
#pragma unroll
                for(int nt=0;nt<4;nt++){
                    bf[nt][0]=Bs[ks*8+tig  ][wn*32+nt*8+g];
                    bf[nt][1]=Bs[ks*8+tig+4][wn*32+nt*8+g];
                }
#pragma unroll
                for(int mt=0;mt<4;mt++)
#pragma unroll
                    for(int nt=0;nt<4;nt++)
                        mma8(acc[mt][nt], af[mt], bf[nt]);
            }
        }
        // epilogue: leakyrelu + dot(w2) partials
#pragma unroll
        for(int mt=0;mt<4;mt++){
#pragma unroll
            for(int nt=0;nt<4;nt++){
                const int col=nc*128+wn*32+nt*8+2*tig;
                const float bb0=__ldg(b1+col),  bb1=__ldg(b1+col+1);
                const float ww0=__ldg(w2+col),  ww1=__ldg(w2+col+1);
                float v;
                v=acc[mt][nt][0]+bb0; v=v>0.f?v:0.01f*v; wp[mt][0]+=v*ww0;
                v=acc[mt][nt][1]+bb1; v=v>0.f?v:0.01f*v; wp[mt][0]+=v*ww1;
                v=acc[mt][nt][2]+bb0; v=v>0.f?v:0.01f*v; wp[mt][1]+=v*ww0;
                v=acc[mt][nt][3]+bb1; v=v>0.f?v:0.01f*v; wp[mt][1]+=v*ww1;
            }
        }
    }
    // reduce across tig (quad) then across wn warps via smem atomics
#pragma unroll
    for(int mt=0;mt<4;mt++){
        wp[mt][0]+=__shfl_xor_sync(0xffffffffu,wp[mt][0],1);
        wp[mt][0]+=__shfl_xor_sync(0xffffffffu,wp[mt][0],2);
        wp[mt][1]+=__shfl_xor_sync(0xffffffffu,wp[mt][1],1);
        wp[mt][1]+=__shfl_xor_sync(0xffffffffu,wp[mt][1],2);
        if(tig==0){
            atomicAdd(&wps[wm*64+mt*16+g],   wp[mt][0]);
            atomicAdd(&wps[wm*64+mt*16+g+8], wp[mt][1]);
        }
    }
    __syncthreads();
    if(tid<128) g_w[m0+tid]=wps[tid];
}

// ---------------- K2: masked softmax over S -> tma ----------------
__global__ __launch_bounds__(256) void k_softw(const int* __restrict__ seq,
                                               const float* __restrict__ b2)
{
    const int b = blockIdx.x, tid = threadIdx.x;
    const int lane = tid & 31, wid = tid >> 5;
    __shared__ float shm[8], shs[8];
    const bool act = tid < SN;
    float myw = NEGV;
    if (act){
        const int m = b*SN + tid;
        myw = (seq[m]==0) ? NEGV : (g_w[m] + b2[0]);
    }
    float v = wmax(myw);
    if (lane==0) shm[wid] = v;
    __syncthreads();
    float mx = shm[0];
#pragma unroll
    for (int i=1;i<8;i++) mx = fmaxf(mx, shm[i]);
    float e = act ? expf(myw - mx) : 0.f;
    float s = wsum(e);
    if (lane==0) shs[wid] = s;
    __syncthreads();
    float tot = shs[0];
#pragma unroll
    for (int i=1;i<8;i++) tot += shs[i];
    if (act) g_tma[b*SN + tid] = e / tot;
}

// ============================================================================
// K3: gates GEMM in 3xTF32 (fp32-equivalent; argmax must be exact-ish)
// + softmax out + argmax count + bij init
// ============================================================================
__global__ __launch_bounds__(256) void k_gates_tc(
    const float* __restrict__ X, const int* __restrict__ seq,
    const float* __restrict__ AW, float* __restrict__ og)
{
    __shared__ uint32_t Ah[128][36];
    __shared__ uint32_t Al[128][36];
    __shared__ uint32_t Bh[32][36];
    __shared__ uint32_t Bl[32][36];
    const int tid=threadIdx.x, lane=tid&31, wid=tid>>5;
    const int g=lane>>2, tig=lane&3;
    const int m0=blockIdx.x*128;
    const int lar=tid>>3, lac=(tid&7)*4;   // A loader
    const int lba=tid>>3, lbk=(tid&7)*4;   // B loader: aspect row, k col

    float acc[4][4];
#pragma unroll
    for(int nt=0;nt<4;nt++)
#pragma unroll
        for(int c=0;c<4;c++) acc[nt][c]=0.f;

    float4 ra[4]; float4 rb;
#pragma unroll
    for(int it=0;it<4;it++)
        ra[it]=*(const float4*)(X+(size_t)(m0+lar+it*32)*HN+lac);
    rb=*(const float4*)(AW+(size_t)lba*HN+lbk);

#pragma unroll 1
    for(int kt=0;kt<16;kt++){
        __syncthreads();
#pragma unroll
        for(int it=0;it<4;it++){
            uint4 h,l;
            tfsplit(ra[it].x,h.x,l.x); tfsplit(ra[it].y,h.y,l.y);
            tfsplit(ra[it].z,h.z,l.z); tfsplit(ra[it].w,h.w,l.w);
            *(uint4*)&Ah[lar+it*32][lac]=h;
            *(uint4*)&Al[lar+it*32][lac]=l;
        }
        {
            uint4 h,l;
            tfsplit(rb.x,h.x,l.x); tfsplit(rb.y,h.y,l.y);
            tfsplit(rb.z,h.z,l.z); tfsplit(rb.w,h.w,l.w);
            *(uint4*)&Bh[lba][lbk]=h;
            *(uint4*)&Bl[lba][lbk]=l;
        }
        __syncthreads();
        if(kt<15){
            const int k0=(kt+1)*32;
#pragma unroll
            for(int it=0;it<4;it++)
                ra[it]=*(const float4*)(X+(size_t)(m0+lar+it*32)*HN+k0+lac);
            rb=*(const float4*)(AW+(size_t)lba*HN+k0+lbk);
        }
#pragma unroll
        for(int ks=0;ks<4;ks++){
            uint32_t ah[4],al[4],bh[4][2],bl[4][2];
            const int r0=wid*16;
            ah[0]=Ah[r0+g  ][ks*8+tig]; ah[1]=Ah[r0+g+8][ks*8+tig];
            ah[2]=Ah[r0+g  ][ks*8+tig+4]; ah[3]=Ah[r0+g+8][ks*8+tig+4];
            al[0]=Al[r0+g  ][ks*8+tig]; al[1]=Al[r0+g+8][ks*8+tig];
            al[2]=Al[r0+g  ][ks*8+tig+4]; al[3]=Al[r0+g+8][ks*8+tig+4];
#pragma unroll
            for(int nt=0;nt<4;nt++){
                bh[nt][0]=Bh[nt*8+g][ks*8+tig]; bh[nt][1]=Bh[nt*8+g][ks*8+tig+4];
                bl[nt][0]=Bl[nt*8+g][ks*8+tig]; bl[nt][1]=Bl[nt*8+g][ks*8+tig+4];
            }
#pragma unroll
            for(int nt=0;nt<4;nt++){
                mma8(acc[nt], al, bh[nt]);   // small terms first
                mma8(acc[nt], ah, bl[nt]);
                mma8(acc[nt], ah, bh[nt]);
            }
        }
    }
    // stage gates into smem (reuse Ah), then row-wise epilogue
    __syncthreads();
    float* sg=(float*)&Ah[0][0];          // stride 36
#pragma unroll
    for(int nt=0;nt<4;nt++){
        const int r0=wid*16, c0=nt*8+2*tig;
        sg[(r0+g  )*36+c0  ]=acc[nt][0];
        sg[(r0+g  )*36+c0+1]=acc[nt][1];
        sg[(r0+g+8)*36+c0  ]=acc[nt][2];
        sg[(r0+g+8)*36+c0+1]=acc[nt][3];
    }
    __syncthreads();
    if(tid<128){
        const int m=m0+tid;
        float v[32];
#pragma unroll
        for(int a=0;a<32;a++) v[a]=sg[tid*36+a];
        float mx=v[0]; int am=0;
#pragma unroll
        for(int a=1;a<32;a++) if(v[a]>mx){mx=v[a];am=a;}
        float ex[32]; float s=0.f;
#pragma unroll
        for(int a=0;a<32;a++){ ex[a]=expf(v[a]-mx); s+=ex[a]; }
        const float inv=1.f/s;
#pragma unroll
        for(int a=0;a<32;a++){
            og[(size_t)m*AN+a]=ex[a]*inv;
            g_bij[(size_t)m*AN+a]=v[a];
        }
        if(seq[m]!=0) atomicAdd(&g_cnt[(m/SN)*AN+am],1);
    }
}

// ============================================================================
// K4: moe GEMM (TF32 tensor core) + tanh + residual (pre-LN)
// grid (nc=4, mtile=800): nc-siblings adjacent for L2 reuse of X tile.
// ============================================================================
__global__ __launch_bounds__(256) void k_moe_tc(
    const float* __restrict__ X, const float* __restrict__ W,
    const float* __restrict__ bL)
{
    __shared__ uint32_t As[128][36];
    __shared__ uint32_t Bs[32][132];
    const int tid=threadIdx.x, lane=tid&31, wid=tid>>5;
    const int wm=wid>>2, wn=wid&3, g=lane>>2, tig=lane&3;
    const int nc=blockIdx.x;
    const int m0=blockIdx.y*128;
    const int n0b=nc*128;
    const int lar=tid>>3, lac=(tid&7)*4;
    const int lbk=tid>>5, lbc=(tid&31)*4;

    float acc[4][4][4];
#pragma unroll
    for(int mt=0;mt<4;mt++)
#pragma unroll
        for(int nt=0;nt<4;nt++)
#pragma unroll
            for(int c=0;c<4;c++) acc[mt][nt][c]=0.f;

    float4 ra[4], rb[4];
#pragma unroll
    for(int it=0;it<4;it++)
        ra[it]=*(const float4*)(X+(size_t)(m0+lar+it*32)*HN+lac);
#pragma unroll
    for(int it=0;it<4;it++)
        rb[it]=*(const float4*)(W+(size_t)(lbk+it*8)*HN+n0b+lbc);

#pragma unroll 1
    for(int kt=0;kt<16;kt++){
        __syncthreads();
#pragma unroll
        for(int it=0;it<4;it++)
            *(uint4*)&As[lar+it*32][lac] =
                make_uint4(f2tf(ra[it].x),f2tf(ra[it].y),f2tf(ra[it].z),f2tf(ra[it].w));
#pragma unroll
        for(int it=0;it<4;it++)
            *(uint4*)&Bs[lbk+it*8][lbc] =
                make_uint4(f2tf(rb[it].x),f2tf(rb[it].y),f2tf(rb[it].z),f2tf(rb[it].w));
        __syncthreads();
        if(kt<15){
            const int k0=(kt+1)*32;
#pragma unroll
            for(int it=0;it<4;it++)
                ra[it]=*(const float4*)(X+(size_t)(m0+lar+it*32)*HN+k0+lac);
#pragma unroll
            for(int it=0;it<4;it++)
                rb[it]=*(const float4*)(W+(size_t)(k0+lbk+it*8)*HN+n0b+lbc);
        }
#pragma unroll
        for(int ks=0;ks<4;ks++){
            uint32_t af[4][4], bf[4][2];
#pragma unroll
            for(int mt=0;mt<4;mt++){
                const int r0=wm*64+mt*16;
                af[mt][0]=As[r0+g  ][ks*8+tig];
                af[mt][1]=As[r0+g+8][ks*8+tig];
                af[mt][2]=As[r0+g  ][ks*8+tig+4];
                af[mt][3]=As[r0+g+8][ks*8+tig+4];
            }
#pragma unroll
            for(int nt=0;nt<4;nt++){
                bf[nt][0]=Bs[ks*8+tig  ][wn*32+nt*8+g];
                bf[nt][1]=Bs[ks*8+tig+4][wn*32+nt*8+g];
            }
#pragma unroll
            for(int mt=0;mt<4;mt++)
#pragma unroll
                for(int nt=0;nt<4;nt++)
                    mma8(acc[mt][nt], af[mt], bf[nt]);
        }
    }
    // epilogue: tanh + residual
#pragma unroll
    for(int mt=0;mt<4;mt++){
        const int row=m0+wm*64+mt*16+g;
#pragma unroll
        for(int nt=0;nt<4;nt++){
            const int col=n0b+wn*32+nt*8+2*tig;
            const float bb0=__ldg(bL+col), bb1=__ldg(bL+col+1);
            const size_t i0=(size_t)row*HN+col, i1=(size_t)(row+8)*HN+col;
            g_moe[i0]  =tanhf(acc[mt][nt][0]+bb0)+__ldg(X+i0);
            g_moe[i0+1]=tanhf(acc[mt][nt][1]+bb1)+__ldg(X+i0+1);
            g_moe[i1]  =tanhf(acc[mt][nt][2]+bb0)+__ldg(X+i1);
            g_moe[i1+1]=tanhf(acc[mt][nt][3]+bb1)+__ldg(X+i1+1);
        }
    }
}

// ---------------- K5: LayerNorm in place on g_moe ----------------
__global__ __launch_bounds__(128) void k_ln(const float* __restrict__ gam,
                                            const float* __restrict__ bet)
{
    const int row = blockIdx.x, tid = threadIdx.x;
    const int lane = tid & 31, wid = tid >> 5;
    __shared__ float sh1[4], sh2[4];
    float4 x = reinterpret_cast<const float4*>(g_moe)[(size_t)row*128 + tid];
    float s = x.x + x.y + x.z + x.w;
    s = wsum(s);
    if (lane==0) sh1[wid] = s;
    __syncthreads();
    const float mu = (sh1[0]+sh1[1]+sh1[2]+sh1[3]) * (1.f/512.f);
    const float d0=x.x-mu, d1=x.y-mu, d2=x.z-mu, d3=x.w-mu;
    float q = d0*d0 + d1*d1 + d2*d2 + d3*d3;
    q = wsum(q);
    if (lane==0) sh2[wid] = q;
    __syncthreads();
    const float var = (sh2[0]+sh2[1]+sh2[2]+sh2[3]) * (1.f/512.f);
    const float r = rsqrtf(var + 1e-12f);
    float4 gg = __ldg(reinterpret_cast<const float4*>(gam) + tid);
    float4 bb = __ldg(reinterpret_cast<const float4*>(bet) + tid);
    float4 o;
    o.x = d0*r*gg.x + bb.x;
    o.y = d1*r*gg.y + bb.y;
    o.z = d2*r*gg.z + bb.z;
    o.w = d3*r*gg.w + bb.w;
    reinterpret_cast<float4*>(g_moe)[(size_t)row*128 + tid] = o;
}

// ---------------- mask output ----------------
__global__ void k_mask(float* __restrict__ om){
    int i = blockIdx.x*256 + threadIdx.x;
    if (i < BN*AN) om[i] = (g_cnt[i]==0) ? 1.f : 0.f;
}

// ---------------- routing: cap = einsum(masked-softmax(bij)*tma, moe) + squash ----------------
__global__ __launch_bounds__(256) void k_cap(const int* __restrict__ seq,
                                             float* __restrict__ oc){
    __shared__ __align__(16) float Ms[8][512];
    __shared__ __align__(16) float Ct[8][32];
    const int b = blockIdx.x, tid = threadIdx.x;
    const int lane = tid & 31, ty = tid >> 5;
    float acc[4][16];
#pragma unroll
    for (int a=0;a<4;a++)
#pragma unroll
        for (int t=0;t<16;t++) acc[a][t] = 0.f;

    for (int st=0; st<SN; st+=8){
        __syncthreads();
#pragma unroll
        for (int k=0;k<4;k++){
            const int f  = tid + k*256;
            const int rr = f >> 7;
            const int cc = (f & 127) << 2;
            *reinterpret_cast<float4*>(&Ms[rr][cc]) =
                *reinterpret_cast<const float4*>(&g_moe[(size_t)(b*SN + st + rr)*HN + cc]);
        }
        {
            const size_t m = (size_t)b*SN + st + ty;
            float x = g_bij[m*AN + lane];
            if (g_cnt[b*AN + lane] == 0) x = NEGV;
            const float mx = wmax(x);
            const float e  = expf(x - mx);
            const float sm = wsum(e);
            float cij = (seq[m]==0) ? 0.f : e/sm;
            Ct[ty][lane] = cij * g_tma[m];
        }
        __syncthreads();
#pragma unroll
        for (int sp=0; sp<8; sp++){
            float4 c4 = *reinterpret_cast<const float4*>(&Ct[sp][ty*4]);
            float cv[4] = {c4.x, c4.y, c4.z, c4.w};
#pragma unroll
            for (int j=0;j<4;j++){
                float4 mv = *reinterpret_cast<const float4*>(&Ms[sp][lane*4 + j*128]);
#pragma unroll
                for (int a=0;a<4;a++){
                    acc[a][j*4+0] += cv[a]*mv.x;
                    acc[a][j*4+1] += cv[a]*mv.y;
                    acc[a][j*4+2] += cv[a]*mv.z;
                    acc[a][j*4+3] += cv[a]*mv.w;
                }
            }
        }
    }
#pragma unroll
    for (int a=0;a<4;a++){
        float q = 0.f;
#pragma unroll
        for (int t=0;t<16;t++) q += acc[a][t]*acc[a][t];
        q = wsum(q);
        const float sc = q/(1.f+q) * rsqrtf(q + 1e-9f);
        const int ga = b*AN + ty*4 + a;
#pragma unroll
        for (int j=0;j<4;j++){
            float4 o = make_float4(acc[a][j*4+0]*sc, acc[a][j*4+1]*sc,
                                   acc[a][j*4+2]*sc, acc[a][j*4+3]*sc);
            *reinterpret_cast<float4*>(&oc[(size_t)ga*HN + lane*4 + j*128]) = o;
        }
    }
}

// ---------------- routing: bij += moe . cap^T ----------------
__global__ __launch_bounds__(256) void k_bup(const float* __restrict__ cap){
    const int b = blockIdx.x, s = threadIdx.x;
    if (s >= SN) return;
    const size_t m = (size_t)b*SN + s;
    const float4* xr = reinterpret_cast<const float4*>(g_moe + m*HN);
    const float4* cr = reinterpret_cast<const float4*>(cap + (size_t)b*AN*HN);
    float accb[32];
#pragma unroll
    for (int a=0;a<32;a++) accb[a] = 0.f;
    for (int k4=0;k4<128;k4++){
        float4 x = xr[k4];
#pragma unroll
        for (int a=0;a<32;a++){
            float4 c = __ldg(&cr[a*128 + k4]);
            accb[a] += x.x*c.x + x.y*c.y + x.z*c.z + x.w*c.w;
        }
    }
#pragma unroll
    for (int a=0;a<32;a++) g_bij[m*AN + a] += accb[a];
}

// ---------------- launch ----------------
extern "C" void kernel_launch(void* const* d_in, const int* in_sizes, int n_in,
                              void* d_out, int out_size)
{
    const float* item_emb = (const float*)d_in[0];
    const int*   item_seq = (const int*)  d_in[1];
    const float* pos_emb  = (const float*)d_in[2];
    const float* attn_w1  = (const float*)d_in[3];
    const float* attn_b1  = (const float*)d_in[4];
    const float* attn_w2  = (const float*)d_in[5];
    const float* attn_b2  = (const float*)d_in[6];
    const float* lin_w    = (const float*)d_in[7];
    const float* lin_b    = (const float*)d_in[8];
    const float* aspect_w = (const float*)d_in[9];
    const float* ln_g     = (const float*)d_in[10];
    const float* ln_b     = (const float*)d_in[11];

    float* out       = (float*)d_out;
    float* out_cap   = out;                                   // B*A*H
    float* out_gates = out + (size_t)BN*AN*HN;                // B*S*A
    float* out_mask  = out_gates + (size_t)BN*SN*AN;          // B*A

    k_zero<<<64,256>>>();
    k_attn_tc<<<800,256>>>(item_emb, pos_emb, attn_w1, attn_b1, attn_w2);
    k_softw<<<BN,256>>>(item_seq, attn_b2);
    k_gates_tc<<<800,256>>>(item_emb, item_seq, aspect_w, out_gates);
    dim3 gmoe(4,800);
    k_moe_tc<<<gmoe,256>>>(item_emb, lin_w, lin_b);
    k_ln<<<MN,128>>>(ln_g, ln_b);
    k_mask<<<64,256>>>(out_mask);
    for (int it=0; it<3; it++){
        k_cap<<<BN,256>>>(item_seq, out_cap);
        if (it < 2) k_bup<<<BN,256>>>(out_cap);
    }
}

// round 5
// speedup vs baseline: 1.7964x; 1.0488x over previous
#include <cuda_runtime.h>
#include <math.h>
#include <stdint.h>

#define BN 512
#define SN 200
#define HN 512
#define AN 32
#define MN (BN*SN)          // 102400
#define NEGV (-1e9f)

// ---------------- scratch (no allocations allowed) ----------------
__device__ float g_moe[(size_t)MN*HN];   // 210 MB
__device__ float g_bij[MN*AN];
__device__ float g_w[MN];
__device__ float g_tma[MN];
__device__ int   g_cnt[BN*AN];

__device__ __forceinline__ float wsum(float v){
#pragma unroll
    for (int o=16;o;o>>=1) v += __shfl_xor_sync(0xffffffffu, v, o);
    return v;
}
__device__ __forceinline__ float wmax(float v){
#pragma unroll
    for (int o=16;o;o>>=1) v = fmaxf(v, __shfl_xor_sync(0xffffffffu, v, o));
    return v;
}
__device__ __forceinline__ uint32_t f2tf(float f){
    uint32_t r; asm("cvt.rna.tf32.f32 %0, %1;" : "=r"(r) : "f"(f)); return r;
}
__device__ __forceinline__ void tfsplit(float x, uint32_t& h, uint32_t& l){
    h = f2tf(x);
    l = f2tf(x - __uint_as_float(h));
}
__device__ __forceinline__ void mma8(float* c, const uint32_t* a, const uint32_t* b){
    asm volatile("mma.sync.aligned.m16n8k8.row.col.f32.tf32.tf32.f32 "
      "{%0,%1,%2,%3},{%4,%5,%6,%7},{%8,%9},{%0,%1,%2,%3};"
      : "+f"(c[0]),"+f"(c[1]),"+f"(c[2]),"+f"(c[3])
      : "r"(a[0]),"r"(a[1]),"r"(a[2]),"r"(a[3]),"r"(b[0]),"r"(b[1]));
}
__device__ __forceinline__ uint32_t smem_u32(const void* p){
    uint32_t a;
    asm("{ .reg .u64 t; cvta.to.shared.u64 t, %1; cvt.u32.u64 %0, t; }" : "=r"(a) : "l"(p));
    return a;
}
__device__ __forceinline__ void cp16(uint32_t d, const void* s){
    asm volatile("cp.async.cg.shared.global [%0],[%1],16;" :: "r"(d), "l"(s));
}
#define CPCOMMIT() asm volatile("cp.async.commit_group;")
#define CPWAIT1()  asm volatile("cp.async.wait_group 1;")
#define CPWAIT0()  asm volatile("cp.async.wait_group 0;")

// GEMM tile geometry: block 128M x 256N, K staged in 32s, 8 warps of 64x64
#define AW_STRIDE 36     // words per A row  (32 k + pad4)
#define BW_STRIDE 264    // words per B row  (256 n + pad8)
#define A_BUF_W  (128*AW_STRIDE)   // 4608 words
#define B_BUF_W  (32*BW_STRIDE)    // 8448 words
#define SM_WORDS (2*A_BUF_W + 2*B_BUF_W)   // 26112 words = 104448 B

// ---------------- K0: zero counts + g_w ----------------
__global__ void k_zero(){
    int i = blockIdx.x*256 + threadIdx.x;
    if (i < BN*AN) g_cnt[i] = 0;
    if (i < MN)    g_w[i]   = 0.f;
}

// ============================================================================
// K1: attention GEMM (tf32, 64x64 warp tiles, cp.async B) + leakyrelu + dot(w2)
// grid (2 nc, 800 m); partial row sums accumulated to g_w via atomicAdd.
// ============================================================================
__global__ __launch_bounds__(256,1) void k_attn_tc(
    const float* __restrict__ X, const float* __restrict__ P,
    const float* __restrict__ W1, const float* __restrict__ b1,
    const float* __restrict__ w2)
{
    extern __shared__ uint32_t sm[];
    uint32_t* As = sm;                  // [2][128][36]
    uint32_t* Bs = sm + 2*A_BUF_W;      // [2][32][264]
    const uint32_t smb = smem_u32(sm);
    const int tid=threadIdx.x, lane=tid&31, wid=tid>>5;
    const int wm=wid>>2, wn=wid&3, g=lane>>2, t=lane&3;
    const int n0=blockIdx.x*256, m0=blockIdx.y*128;

    // A loader (register path, X+P): 2 threads/row, 4 float4 each
    const int arow=tid>>1, afb=(tid&1)*4;      // float4 base index (0 or 4)
    const int srow=(m0+arow)%SN;
    const float* Xr = X + (size_t)(m0+arow)*HN;
    const float* Pr = P + (size_t)srow*HN;
    // B loader (cp.async): 8 threads/row, 8 float4 each (stride 8 f4)
    const int brow=tid>>3, bfb=tid&7;
    const uint32_t boffB = (uint32_t)(brow*BW_STRIDE + bfb*4)*4;
    const uint32_t bBuf[2] = { smb + (uint32_t)(2*A_BUF_W)*4 + boffB,
                               smb + (uint32_t)(2*A_BUF_W + B_BUF_W)*4 + boffB };
    const float* Bsrc0 = W1 + (size_t)brow*HN + n0 + bfb*4;

    float acc[4][8][4];
#pragma unroll
    for(int mt=0;mt<4;mt++)
#pragma unroll
        for(int nt=0;nt<8;nt++)
#pragma unroll
            for(int c=0;c<4;c++) acc[mt][nt][c]=0.f;

    // prologue: A regs kt0, B cp kt0 -> buf0
    float4 ra[4];
#pragma unroll
    for(int j=0;j<4;j++){
        float4 xv=*(const float4*)(Xr + (afb+j)*4);
        float4 pv=*(const float4*)(Pr + (afb+j)*4);
        ra[j]=make_float4(xv.x+pv.x,xv.y+pv.y,xv.z+pv.z,xv.w+pv.w);
    }
#pragma unroll
    for(int j=0;j<8;j++) cp16(bBuf[0]+j*128, Bsrc0 + j*32);
    CPCOMMIT();

#pragma unroll 1
    for(int kt=0;kt<16;kt++){
        const int cur=kt&1;
        __syncthreads();   // prev mma done: safe to overwrite As[cur], issue into Bs[cur^1]
        {   // STS A (cvt.rna at store -> smem holds tf32)
            uint32_t* dst = As + cur*A_BUF_W + arow*AW_STRIDE + afb*4;
#pragma unroll
            for(int j=0;j<4;j++)
                *(uint4*)(dst + j*4) =
                    make_uint4(f2tf(ra[j].x),f2tf(ra[j].y),f2tf(ra[j].z),f2tf(ra[j].w));
        }
        if(kt<15){
            const int k0=(kt+1)*32;
            const float* bsrc = W1 + (size_t)(k0+brow)*HN + n0 + bfb*4;
#pragma unroll
            for(int j=0;j<8;j++) cp16(bBuf[cur^1]+j*128, bsrc + j*32);
            CPCOMMIT();
#pragma unroll
            for(int j=0;j<4;j++){
                float4 xv=*(const float4*)(Xr + k0 + (afb+j)*4);
                float4 pv=*(const float4*)(Pr + k0 + (afb+j)*4);
                ra[j]=make_float4(xv.x+pv.x,xv.y+pv.y,xv.z+pv.z,xv.w+pv.w);
            }
        }
        if(kt<15) CPWAIT1(); else CPWAIT0();
        __syncthreads();

        const uint32_t* Ab = As + cur*A_BUF_W;
        const uint32_t* Bb = Bs + cur*B_BUF_W;
#pragma unroll
        for(int ks=0;ks<4;ks++){
            uint32_t af[4][4], bf[8][2];
#pragma unroll
            for(int mt=0;mt<4;mt++){
                const int r0=wm*64+mt*16;
                const uint32_t* p0=Ab+(r0+g  )*AW_STRIDE+ks*8+t;
                const uint32_t* p1=Ab+(r0+g+8)*AW_STRIDE+ks*8+t;
                af[mt][0]=p0[0]; af[mt][1]=p1[0]; af[mt][2]=p0[4]; af[mt][3]=p1[4];
            }
#pragma unroll
            for(int nt=0;nt<8;nt++){
                const int c=wn*64+nt*8+g;
                bf[nt][0]=f2tf(__uint_as_float(Bb[(ks*8+t  )*BW_STRIDE+c]));
                bf[nt][1]=f2tf(__uint_as_float(Bb[(ks*8+t+4)*BW_STRIDE+c]));
            }
#pragma unroll
            for(int mt=0;mt<4;mt++)
#pragma unroll
                for(int nt=0;nt<8;nt++)
                    mma8(acc[mt][nt], af[mt], bf[nt]);
        }
    }

    // epilogue: leakyrelu + dot(w2) partials; reduce over quad, atomicAdd g_w
#pragma unroll
    for(int mt=0;mt<4;mt++){
        float wp0=0.f, wp1=0.f;
#pragma unroll
        for(int nt=0;nt<8;nt++){
            const int col=n0+wn*64+nt*8+2*t;
            const float bb0=__ldg(b1+col), bb1=__ldg(b1+col+1);
            const float ww0=__ldg(w2+col), ww1=__ldg(w2+col+1);
            float v;
            v=acc[mt][nt][0]+bb0; v=v>0.f?v:0.01f*v; wp0+=v*ww0;
            v=acc[mt][nt][1]+bb1; v=v>0.f?v:0.01f*v; wp0+=v*ww1;
            v=acc[mt][nt][2]+bb0; v=v>0.f?v:0.01f*v; wp1+=v*ww0;
            v=acc[mt][nt][3]+bb1; v=v>0.f?v:0.01f*v; wp1+=v*ww1;
        }
        wp0+=__shfl_xor_sync(0xffffffffu,wp0,1); wp0+=__shfl_xor_sync(0xffffffffu,wp0,2);
        wp1+=__shfl_xor_sync(0xffffffffu,wp1,1); wp1+=__shfl_xor_sync(0xffffffffu,wp1,2);
        if(t==0){
            const int r=m0+wm*64+mt*16+g;
            atomicAdd(&g_w[r],   wp0);
            atomicAdd(&g_w[r+8], wp1);
        }
    }
}

// ============================================================================
// K4: moe GEMM (tf32, 64x64 warp tiles, cp.async A+B) + tanh + residual
// grid (2 nc, 800 m)
// ============================================================================
__global__ __launch_bounds__(256,1) void k_moe_tc(
    const float* __restrict__ X, const float* __restrict__ W,
    const float* __restrict__ bL)
{
    extern __shared__ uint32_t sm[];
    uint32_t* As = sm;
    uint32_t* Bs = sm + 2*A_BUF_W;
    const uint32_t smb = smem_u32(sm);
    const int tid=threadIdx.x, lane=tid&31, wid=tid>>5;
    const int wm=wid>>2, wn=wid&3, g=lane>>2, t=lane&3;
    const int n0=blockIdx.x*256, m0=blockIdx.y*128;

    const int arow=tid>>1, afb=(tid&1)*4;
    const uint32_t aoffB = (uint32_t)(arow*AW_STRIDE + afb*4)*4;
    const uint32_t aBuf[2] = { smb + aoffB, smb + (uint32_t)A_BUF_W*4 + aoffB };
    const float* Asrc0 = X + (size_t)(m0+arow)*HN + afb*4;

    const int brow=tid>>3, bfb=tid&7;
    const uint32_t boffB = (uint32_t)(brow*BW_STRIDE + bfb*4)*4;
    const uint32_t bBuf[2] = { smb + (uint32_t)(2*A_BUF_W)*4 + boffB,
                               smb + (uint32_t)(2*A_BUF_W + B_BUF_W)*4 + boffB };
    const float* Bsrc0 = W + (size_t)brow*HN + n0 + bfb*4;

    float acc[4][8][4];
#pragma unroll
    for(int mt=0;mt<4;mt++)
#pragma unroll
        for(int nt=0;nt<8;nt++)
#pragma unroll
            for(int c=0;c<4;c++) acc[mt][nt][c]=0.f;

    // prologue kt0 -> buf0
#pragma unroll
    for(int j=0;j<4;j++) cp16(aBuf[0]+j*16, Asrc0 + j*4);
#pragma unroll
    for(int j=0;j<8;j++) cp16(bBuf[0]+j*128, Bsrc0 + j*32);
    CPCOMMIT();

#pragma unroll 1
    for(int kt=0;kt<16;kt++){
        const int cur=kt&1;
        __syncthreads();
        if(kt<15){
            const int k0=(kt+1)*32;
            const float* asrc = X + (size_t)(m0+arow)*HN + k0 + afb*4;
            const float* bsrc = W + (size_t)(k0+brow)*HN + n0 + bfb*4;
#pragma unroll
            for(int j=0;j<4;j++) cp16(aBuf[cur^1]+j*16, asrc + j*4);
#pragma unroll
            for(int j=0;j<8;j++) cp16(bBuf[cur^1]+j*128, bsrc + j*32);
            CPCOMMIT();
        }
        if(kt<15) CPWAIT1(); else CPWAIT0();
        __syncthreads();

        const uint32_t* Ab = As + cur*A_BUF_W;
        const uint32_t* Bb = Bs + cur*B_BUF_W;
#pragma unroll
        for(int ks=0;ks<4;ks++){
            uint32_t af[4][4], bf[8][2];
#pragma unroll
            for(int mt=0;mt<4;mt++){
                const int r0=wm*64+mt*16;
                const uint32_t* p0=Ab+(r0+g  )*AW_STRIDE+ks*8+t;
                const uint32_t* p1=Ab+(r0+g+8)*AW_STRIDE+ks*8+t;
                af[mt][0]=f2tf(__uint_as_float(p0[0]));
                af[mt][1]=f2tf(__uint_as_float(p1[0]));
                af[mt][2]=f2tf(__uint_as_float(p0[4]));
                af[mt][3]=f2tf(__uint_as_float(p1[4]));
            }
#pragma unroll
            for(int nt=0;nt<8;nt++){
                const int c=wn*64+nt*8+g;
                bf[nt][0]=f2tf(__uint_as_float(Bb[(ks*8+t  )*BW_STRIDE+c]));
                bf[nt][1]=f2tf(__uint_as_float(Bb[(ks*8+t+4)*BW_STRIDE+c]));
            }
#pragma unroll
            for(int mt=0;mt<4;mt++)
#pragma unroll
                for(int nt=0;nt<8;nt++)
                    mma8(acc[mt][nt], af[mt], bf[nt]);
        }
    }

    // epilogue: tanh + residual
#pragma unroll
    for(int mt=0;mt<4;mt++){
        const int ra=m0+wm*64+mt*16+g, rb=ra+8;
#pragma unroll
        for(int nt=0;nt<8;nt++){
            const int col=n0+wn*64+nt*8+2*t;
            const float bb0=__ldg(bL+col), bb1=__ldg(bL+col+1);
            const size_t i0=(size_t)ra*HN+col, i1=(size_t)rb*HN+col;
            g_moe[i0]  =tanhf(acc[mt][nt][0]+bb0)+__ldg(X+i0);
            g_moe[i0+1]=tanhf(acc[mt][nt][1]+bb1)+__ldg(X+i0+1);
            g_moe[i1]  =tanhf(acc[mt][nt][2]+bb0)+__ldg(X+i1);
            g_moe[i1+1]=tanhf(acc[mt][nt][3]+bb1)+__ldg(X+i1+1);
        }
    }
}

// ---------------- K2: masked softmax over S -> tma ----------------
__global__ __launch_bounds__(256) void k_softw(const int* __restrict__ seq,
                                               const float* __restrict__ b2)
{
    const int b = blockIdx.x, tid = threadIdx.x;
    const int lane = tid & 31, wid = tid >> 5;
    __shared__ float shm[8], shs[8];
    const bool act = tid < SN;
    float myw = NEGV;
    if (act){
        const int m = b*SN + tid;
        myw = (seq[m]==0) ? NEGV : (g_w[m] + b2[0]);
    }
    float v = wmax(myw);
    if (lane==0) shm[wid] = v;
    __syncthreads();
    float mx = shm[0];
#pragma unroll
    for (int i=1;i<8;i++) mx = fmaxf(mx, shm[i]);
    float e = act ? expf(myw - mx) : 0.f;
    float s = wsum(e);
    if (lane==0) shs[wid] = s;
    __syncthreads();
    float tot = shs[0];
#pragma unroll
    for (int i=1;i<8;i++) tot += shs[i];
    if (act) g_tma[b*SN + tid] = e / tot;
}

// ============================================================================
// K3: gates GEMM in 3xTF32 (fp32-equivalent; argmax must be exact-ish)
// ============================================================================
__global__ __launch_bounds__(256) void k_gates_tc(
    const float* __restrict__ X, const int* __restrict__ seq,
    const float* __restrict__ AW, float* __restrict__ og)
{
    __shared__ uint32_t Ah[128][36];
    __shared__ uint32_t Al[128][36];
    __shared__ uint32_t Bh[32][36];
    __shared__ uint32_t Bl[32][36];
    const int tid=threadIdx.x, lane=tid&31, wid=tid>>5;
    const int g=lane>>2, tig=lane&3;
    const int m0=blockIdx.x*128;
    const int lar=tid>>3, lac=(tid&7)*4;
    const int lba=tid>>3, lbk=(tid&7)*4;

    float acc[4][4];
#pragma unroll
    for(int nt=0;nt<4;nt++)
#pragma unroll
        for(int c=0;c<4;c++) acc[nt][c]=0.f;

    float4 ra[4]; float4 rb;
#pragma unroll
    for(int it=0;it<4;it++)
        ra[it]=*(const float4*)(X+(size_t)(m0+lar+it*32)*HN+lac);
    rb=*(const float4*)(AW+(size_t)lba*HN+lbk);

#pragma unroll 1
    for(int kt=0;kt<16;kt++){
        __syncthreads();
#pragma unroll
        for(int it=0;it<4;it++){
            uint4 h,l;
            tfsplit(ra[it].x,h.x,l.x); tfsplit(ra[it].y,h.y,l.y);
            tfsplit(ra[it].z,h.z,l.z); tfsplit(ra[it].w,h.w,l.w);
            *(uint4*)&Ah[lar+it*32][lac]=h;
            *(uint4*)&Al[lar+it*32][lac]=l;
        }
        {
            uint4 h,l;
            tfsplit(rb.x,h.x,l.x); tfsplit(rb.y,h.y,l.y);
            tfsplit(rb.z,h.z,l.z); tfsplit(rb.w,h.w,l.w);
            *(uint4*)&Bh[lba][lbk]=h;
            *(uint4*)&Bl[lba][lbk]=l;
        }
        __syncthreads();
        if(kt<15){
            const int k0=(kt+1)*32;
#pragma unroll
            for(int it=0;it<4;it++)
                ra[it]=*(const float4*)(X+(size_t)(m0+lar+it*32)*HN+k0+lac);
            rb=*(const float4*)(AW+(size_t)lba*HN+k0+lbk);
        }
#pragma unroll
        for(int ks=0;ks<4;ks++){
            uint32_t ah[4],al[4],bh[4][2],bl[4][2];
            const int r0=wid*16;
            ah[0]=Ah[r0+g  ][ks*8+tig]; ah[1]=Ah[r0+g+8][ks*8+tig];
            ah[2]=Ah[r0+g  ][ks*8+tig+4]; ah[3]=Ah[r0+g+8][ks*8+tig+4];
            al[0]=Al[r0+g  ][ks*8+tig]; al[1]=Al[r0+g+8][ks*8+tig];
            al[2]=Al[r0+g  ][ks*8+tig+4]; al[3]=Al[r0+g+8][ks*8+tig+4];
#pragma unroll
            for(int nt=0;nt<4;nt++){
                bh[nt][0]=Bh[nt*8+g][ks*8+tig]; bh[nt][1]=Bh[nt*8+g][ks*8+tig+4];
                bl[nt][0]=Bl[nt*8+g][ks*8+tig]; bl[nt][1]=Bl[nt*8+g][ks*8+tig+4];
            }
#pragma unroll
            for(int nt=0;nt<4;nt++){
                mma8(acc[nt], al, bh[nt]);
                mma8(acc[nt], ah, bl[nt]);
                mma8(acc[nt], ah, bh[nt]);
            }
        }
    }
    __syncthreads();
    float* sg=(float*)&Ah[0][0];
#pragma unroll
    for(int nt=0;nt<4;nt++){
        const int r0=wid*16, c0=nt*8+2*tig;
        sg[(r0+g  )*36+c0  ]=acc[nt][0];
        sg[(r0+g  )*36+c0+1]=acc[nt][1];
        sg[(r0+g+8)*36+c0  ]=acc[nt][2];
        sg[(r0+g+8)*36+c0+1]=acc[nt][3];
    }
    __syncthreads();
    if(tid<128){
        const int m=m0+tid;
        float v[32];
#pragma unroll
        for(int a=0;a<32;a++) v[a]=sg[tid*36+a];
        float mx=v[0]; int am=0;
#pragma unroll
        for(int a=1;a<32;a++) if(v[a]>mx){mx=v[a];am=a;}
        float ex[32]; float s=0.f;
#pragma unroll
        for(int a=0;a<32;a++){ ex[a]=expf(v[a]-mx); s+=ex[a]; }
        const float inv=1.f/s;
#pragma unroll
        for(int a=0;a<32;a++){
            og[(size_t)m*AN+a]=ex[a]*inv;
            g_bij[(size_t)m*AN+a]=v[a];
        }
        if(seq[m]!=0) atomicAdd(&g_cnt[(m/SN)*AN+am],1);
    }
}

// ---------------- K5: LayerNorm in place on g_moe ----------------
__global__ __launch_bounds__(128) void k_ln(const float* __restrict__ gam,
                                            const float* __restrict__ bet)
{
    const int row = blockIdx.x, tid = threadIdx.x;
    const int lane = tid & 31, wid = tid >> 5;
    __shared__ float sh1[4], sh2[4];
    float4 x = reinterpret_cast<const float4*>(g_moe)[(size_t)row*128 + tid];
    float s = x.x + x.y + x.z + x.w;
    s = wsum(s);
    if (lane==0) sh1[wid] = s;
    __syncthreads();
    const float mu = (sh1[0]+sh1[1]+sh1[2]+sh1[3]) * (1.f/512.f);
    const float d0=x.x-mu, d1=x.y-mu, d2=x.z-mu, d3=x.w-mu;
    float q = d0*d0 + d1*d1 + d2*d2 + d3*d3;
    q = wsum(q);
    if (lane==0) sh2[wid] = q;
    __syncthreads();
    const float var = (sh2[0]+sh2[1]+sh2[2]+sh2[3]) * (1.f/512.f);
    const float r = rsqrtf(var + 1e-12f);
    float4 gg = __ldg(reinterpret_cast<const float4*>(gam) + tid);
    float4 bb = __ldg(reinterpret_cast<const float4*>(bet) + tid);
    float4 o;
    o.x = d0*r*gg.x + bb.x;
    o.y = d1*r*gg.y + bb.y;
    o.z = d2*r*gg.z + bb.z;
    o.w = d3*r*gg.w + bb.w;
    reinterpret_cast<float4*>(g_moe)[(size_t)row*128 + tid] = o;
}

// ---------------- mask output ----------------
__global__ void k_mask(float* __restrict__ om){
    int i = blockIdx.x*256 + threadIdx.x;
    if (i < BN*AN) om[i] = (g_cnt[i]==0) ? 1.f : 0.f;
}

// ---------------- routing: cap = einsum(masked-softmax(bij)*tma, moe) + squash ----------------
__global__ __launch_bounds__(256) void k_cap(const int* __restrict__ seq,
                                             float* __restrict__ oc){
    __shared__ __align__(16) float Ms[8][512];
    __shared__ __align__(16) float Ct[8][32];
    const int b = blockIdx.x, tid = threadIdx.x;
    const int lane = tid & 31, ty = tid >> 5;
    float acc[4][16];
#pragma unroll
    for (int a=0;a<4;a++)
#pragma unroll
        for (int t=0;t<16;t++) acc[a][t] = 0.f;

    for (int st=0; st<SN; st+=8){
        __syncthreads();
#pragma unroll
        for (int k=0;k<4;k++){
            const int f  = tid + k*256;
            const int rr = f >> 7;
            const int cc = (f & 127) << 2;
            *reinterpret_cast<float4*>(&Ms[rr][cc]) =
                *reinterpret_cast<const float4*>(&g_moe[(size_t)(b*SN + st + rr)*HN + cc]);
        }
        {
            const size_t m = (size_t)b*SN + st + ty;
            float x = g_bij[m*AN + lane];
            if (g_cnt[b*AN + lane] == 0) x = NEGV;
            const float mx = wmax(x);
            const float e  = expf(x - mx);
            const float smv = wsum(e);
            float cij = (seq[m]==0) ? 0.f : e/smv;
            Ct[ty][lane] = cij * g_tma[m];
        }
        __syncthreads();
#pragma unroll
        for (int sp=0; sp<8; sp++){
            float4 c4 = *reinterpret_cast<const float4*>(&Ct[sp][ty*4]);
            float cv[4] = {c4.x, c4.y, c4.z, c4.w};
#pragma unroll
            for (int j=0;j<4;j++){
                float4 mv = *reinterpret_cast<const float4*>(&Ms[sp][lane*4 + j*128]);
#pragma unroll
                for (int a=0;a<4;a++){
                    acc[a][j*4+0] += cv[a]*mv.x;
                    acc[a][j*4+1] += cv[a]*mv.y;
                    acc[a][j*4+2] += cv[a]*mv.z;
                    acc[a][j*4+3] += cv[a]*mv.w;
                }
            }
        }
    }
#pragma unroll
    for (int a=0;a<4;a++){
        float q = 0.f;
#pragma unroll
        for (int t=0;t<16;t++) q += acc[a][t]*acc[a][t];
        q = wsum(q);
        const float sc = q/(1.f+q) * rsqrtf(q + 1e-9f);
        const int ga = b*AN + ty*4 + a;
#pragma unroll
        for (int j=0;j<4;j++){
            float4 o = make_float4(acc[a][j*4+0]*sc, acc[a][j*4+1]*sc,
                                   acc[a][j*4+2]*sc, acc[a][j*4+3]*sc);
            *reinterpret_cast<float4*>(&oc[(size_t)ga*HN + lane*4 + j*128]) = o;
        }
    }
}

// ---------------- routing: bij += moe . cap^T ----------------
__global__ __launch_bounds__(256) void k_bup(const float* __restrict__ cap){
    const int b = blockIdx.x, s = threadIdx.x;
    if (s >= SN) return;
    const size_t m = (size_t)b*SN + s;
    const float4* xr = reinterpret_cast<const float4*>(g_moe + m*HN);
    const float4* cr = reinterpret_cast<const float4*>(cap + (size_t)b*AN*HN);
    float accb[32];
#pragma unroll
    for (int a=0;a<32;a++) accb[a] = 0.f;
    for (int k4=0;k4<128;k4++){
        float4 x = xr[k4];
#pragma unroll
        for (int a=0;a<32;a++){
            float4 c = __ldg(&cr[a*128 + k4]);
            accb[a] += x.x*c.x + x.y*c.y + x.z*c.z + x.w*c.w;
        }
    }
#pragma unroll
    for (int a=0;a<32;a++) g_bij[m*AN + a] += accb[a];
}

// ---------------- launch ----------------
extern "C" void kernel_launch(void* const* d_in, const int* in_sizes, int n_in,
                              void* d_out, int out_size)
{
    const float* item_emb = (const float*)d_in[0];
    const int*   item_seq = (const int*)  d_in[1];
    const float* pos_emb  = (const float*)d_in[2];
    const float* attn_w1  = (const float*)d_in[3];
    const float* attn_b1  = (const float*)d_in[4];
    const float* attn_w2  = (const float*)d_in[5];
    const float* attn_b2  = (const float*)d_in[6];
    const float* lin_w    = (const float*)d_in[7];
    const float* lin_b    = (const float*)d_in[8];
    const float* aspect_w = (const float*)d_in[9];
    const float* ln_g     = (const float*)d_in[10];
    const float* ln_b     = (const float*)d_in[11];

    float* out       = (float*)d_out;
    float* out_cap   = out;                                   // B*A*H
    float* out_gates = out + (size_t)BN*AN*HN;                // B*S*A
    float* out_mask  = out_gates + (size_t)BN*SN*AN;          // B*A

    const size_t smbytes = (size_t)SM_WORDS*4;   // 104448
    cudaFuncSetAttribute(k_attn_tc, cudaFuncAttributeMaxDynamicSharedMemorySize, (int)smbytes);
    cudaFuncSetAttribute(k_moe_tc,  cudaFuncAttributeMaxDynamicSharedMemorySize, (int)smbytes);

    k_zero<<<400,256>>>();
    k_attn_tc<<<dim3(2,800),256,smbytes>>>(item_emb, pos_emb, attn_w1, attn_b1, attn_w2);
    k_softw<<<BN,256>>>(item_seq, attn_b2);
    k_gates_tc<<<800,256>>>(item_emb, item_seq, aspect_w, out_gates);
    k_moe_tc<<<dim3(2,800),256,smbytes>>>(item_emb, lin_w, lin_b);
    k_ln<<<MN,128>>>(ln_g, ln_b);
    k_mask<<<64,256>>>(out_mask);
    for (int it=0; it<3; it++){
        k_cap<<<BN,256>>>(item_seq, out_cap);
        if (it < 2) k_bup<<<BN,256>>>(out_cap);
    }
}